// round 3
// baseline (speedup 1.0000x reference)
#include <cuda_runtime.h>

// Problem constants (fixed by reference: B=1, T=8, C=64, H=W=32, F=10)
#define N_TOK 8192
#define NF 10
#define C_DIM 64
#define M_CHUNKS 32
#define M_CHUNK (N_TOK / M_CHUNKS)     // 256
#define TILE_M 128                     // m's per smem stage (160B each -> 20KB)
#define ATTN_THREADS 128
#define ROWS_PER_THREAD 4              // 2 packed row-pairs
#define ROWS_PER_BLOCK (ATTN_THREADS * ROWS_PER_THREAD)   // 512

// Scratch (static __device__ arrays — no runtime allocation)
__device__ float g_qpair[N_TOK / 2 * 2 * NF];        // pair i,f: {q[2i][f], q[2i+1][f]}
__device__ float g_kv[N_TOK * 40];                   // per m: kk dup pairs (20) | vv dup pairs (20)
__device__ float g_part[M_CHUNKS * N_TOK * NF];      // partial outputs per m-chunk

// ---------------- packed f32x2 helpers ----------------
__device__ __forceinline__ unsigned long long pack2f(float lo, float hi) {
    unsigned long long r;
    asm("mov.b64 %0, {%1, %2};" : "=l"(r) : "f"(lo), "f"(hi));
    return r;
}
__device__ __forceinline__ void unpack2f(unsigned long long p, float& lo, float& hi) {
    asm("mov.b64 {%0, %1}, %2;" : "=f"(lo), "=f"(hi) : "l"(p));
}
__device__ __forceinline__ unsigned long long fma2(unsigned long long a,
                                                   unsigned long long b,
                                                   unsigned long long c) {
    unsigned long long d;
    asm("fma.rn.f32x2 %0, %1, %2, %3;" : "=l"(d) : "l"(a), "l"(b), "l"(c));
    return d;
}
__device__ __forceinline__ unsigned long long mul2(unsigned long long a,
                                                   unsigned long long b) {
    unsigned long long d;
    asm("mul.rn.f32x2 %0, %1, %2;" : "=l"(d) : "l"(a), "l"(b));
    return d;
}
__device__ __forceinline__ unsigned long long relu2(unsigned long long s) {
    float lo, hi;
    unpack2f(s, lo, hi);
    return pack2f(fmaxf(lo, 0.0f), fmaxf(hi, 0.0f));
}

// ---------------- Kernel 1: projections (blockIdx.y selects q/k/v) ----------------
__global__ __launch_bounds__(256) void proj_kernel(
    const float* __restrict__ in1, const float* __restrict__ in2,
    const float* __restrict__ w1, const float* __restrict__ b1,
    const float* __restrict__ w2, const float* __restrict__ b2,
    const float* __restrict__ w3, const float* __restrict__ b3)
{
    __shared__ float ws[NF * C_DIM];          // 2.5 KB
    __shared__ float red[4 * 64 * NF];        // 10 KB

    const int which = blockIdx.y;             // 0=q, 1=k, 2=v
    const float* w    = (which == 0) ? w1 : (which == 1) ? w2 : w3;
    const float* bias = (which == 0) ? b1 : (which == 1) ? b2 : b3;
    const float* x    = (which == 1) ? in2 : in1;

    const int tid = threadIdx.x;
    for (int i = tid; i < NF * C_DIM; i += 256) ws[i] = w[i];
    __syncthreads();

    const int part = tid >> 6;                // 0..3 c-quarter (warp-uniform)
    const int ln   = tid & 63;                // token within block
    const int n    = blockIdx.x * 64 + ln;
    const int t    = n >> 10;
    const int hw   = n & 1023;
    const float* xp = x + t * (C_DIM * 1024) + hw;
    const int c0 = part * 16;

    float acc[NF];
#pragma unroll
    for (int f = 0; f < NF; f++) acc[f] = 0.f;

#pragma unroll
    for (int cc = 0; cc < 16; cc++) {
        const int c = c0 + cc;
        float a = xp[c << 10];
#pragma unroll
        for (int f = 0; f < NF; f++)
            acc[f] = fmaf(ws[f * C_DIM + c], a, acc[f]);
    }
#pragma unroll
    for (int f = 0; f < NF; f++)
        red[part * (64 * NF) + ln * NF + f] = acc[f];
    __syncthreads();

    for (int idx = tid; idx < 64 * NF; idx += 256) {
        const int ln2 = idx / NF;
        const int f   = idx % NF;
        const int nn  = blockIdx.x * 64 + ln2;
        float s = red[idx] + red[64 * NF + idx] + red[2 * 64 * NF + idx]
                + red[3 * 64 * NF + idx] + __ldg(bias + f);
        if (which == 0) {
            // q interleaved pairs: {q[2i][f], q[2i+1][f]}
            g_qpair[(nn >> 1) * (2 * NF) + 2 * f + (nn & 1)] = s;
        } else if (which == 1) {
            g_kv[nn * 40 + 2 * f]     = s;   // kk dup
            g_kv[nn * 40 + 2 * f + 1] = s;
        } else {
            g_kv[nn * 40 + 20 + 2 * f]     = s;  // vv dup
            g_kv[nn * 40 + 20 + 2 * f + 1] = s;
        }
    }
}

// ---------------- Kernel 2: fused relu-attention (packed 2-row pairs) ----------------
// part[chunk][n][f] = sum_{m in chunk} relu(q[n]·k[m]) * v[m][f]
__global__ __launch_bounds__(ATTN_THREADS) void attn_kernel()
{
    __shared__ ulonglong2 skv[TILE_M * 10];   // per m: kk (80B) | vv (80B)

    const int tid   = threadIdx.x;
    const int chunk = blockIdx.y;
    const int p0    = blockIdx.x * (ROWS_PER_BLOCK / 2) + tid * 2;  // first pair index

    const unsigned long long* qp =
        reinterpret_cast<const unsigned long long*>(g_qpair);

    unsigned long long q0[NF], q1[NF], a0[NF], a1[NF];
#pragma unroll
    for (int f = 0; f < NF; f++) {
        q0[f] = qp[(size_t)p0 * NF + f];
        q1[f] = qp[(size_t)(p0 + 1) * NF + f];
        a0[f] = 0ull;
        a1[f] = 0ull;
    }

    const ulonglong2* gkv =
        reinterpret_cast<const ulonglong2*>(g_kv) + (size_t)chunk * M_CHUNK * 10;

    for (int stage = 0; stage < M_CHUNK / TILE_M; ++stage) {
        __syncthreads();
#pragma unroll
        for (int i = tid; i < TILE_M * 10; i += ATTN_THREADS)
            skv[i] = gkv[stage * (TILE_M * 10) + i];
        __syncthreads();

#pragma unroll 2
        for (int m = 0; m < TILE_M; ++m) {
            const ulonglong2* pp = skv + m * 10;
            ulonglong2 k0 = pp[0], k1 = pp[1], k2 = pp[2], k3 = pp[3], k4 = pp[4];

            // packed dots: s = {s_rowA, s_rowB}
            unsigned long long s0 = mul2(q0[0], k0.x);
            unsigned long long s1 = mul2(q1[0], k0.x);
            s0 = fma2(q0[1], k0.y, s0);  s1 = fma2(q1[1], k0.y, s1);
            s0 = fma2(q0[2], k1.x, s0);  s1 = fma2(q1[2], k1.x, s1);
            s0 = fma2(q0[3], k1.y, s0);  s1 = fma2(q1[3], k1.y, s1);
            s0 = fma2(q0[4], k2.x, s0);  s1 = fma2(q1[4], k2.x, s1);
            s0 = fma2(q0[5], k2.y, s0);  s1 = fma2(q1[5], k2.y, s1);
            s0 = fma2(q0[6], k3.x, s0);  s1 = fma2(q1[6], k3.x, s1);
            s0 = fma2(q0[7], k3.y, s0);  s1 = fma2(q1[7], k3.y, s1);
            s0 = fma2(q0[8], k4.x, s0);  s1 = fma2(q1[8], k4.x, s1);
            s0 = fma2(q0[9], k4.y, s0);  s1 = fma2(q1[9], k4.y, s1);

            s0 = relu2(s0);
            s1 = relu2(s1);

            ulonglong2 v0 = pp[5], v1 = pp[6], v2 = pp[7], v3 = pp[8], v4 = pp[9];
            a0[0] = fma2(s0, v0.x, a0[0]);  a1[0] = fma2(s1, v0.x, a1[0]);
            a0[1] = fma2(s0, v0.y, a0[1]);  a1[1] = fma2(s1, v0.y, a1[1]);
            a0[2] = fma2(s0, v1.x, a0[2]);  a1[2] = fma2(s1, v1.x, a1[2]);
            a0[3] = fma2(s0, v1.y, a0[3]);  a1[3] = fma2(s1, v1.y, a1[3]);
            a0[4] = fma2(s0, v2.x, a0[4]);  a1[4] = fma2(s1, v2.x, a1[4]);
            a0[5] = fma2(s0, v2.y, a0[5]);  a1[5] = fma2(s1, v2.y, a1[5]);
            a0[6] = fma2(s0, v3.x, a0[6]);  a1[6] = fma2(s1, v3.x, a1[6]);
            a0[7] = fma2(s0, v3.y, a0[7]);  a1[7] = fma2(s1, v3.y, a1[7]);
            a0[8] = fma2(s0, v4.x, a0[8]);  a1[8] = fma2(s1, v4.x, a1[8]);
            a0[9] = fma2(s0, v4.y, a0[9]);  a1[9] = fma2(s1, v4.y, a1[9]);
        }
    }

    // rows: pair p0 -> rows 2*p0, 2*p0+1 ; pair p0+1 -> rows 2*p0+2, 2*p0+3
    float* o = g_part + (size_t)chunk * (N_TOK * NF) + (size_t)(2 * p0) * NF;
#pragma unroll
    for (int f = 0; f < NF; f++) {
        float lo, hi;
        unpack2f(a0[f], lo, hi);
        o[f]      = lo;          // row 2*p0
        o[NF + f] = hi;          // row 2*p0+1
        unpack2f(a1[f], lo, hi);
        o[2 * NF + f] = lo;      // row 2*p0+2
        o[3 * NF + f] = hi;      // row 2*p0+3
    }
}

// ---------------- Kernel 3: deterministic fixed-order reduce + output permute ----------------
// out[t, f, h, w] = sum_chunks part[chunk][n = t*1024 + hw][f]
__global__ __launch_bounds__(256) void reduce_kernel(float* __restrict__ out)
{
    const int idx = blockIdx.x * blockDim.x + threadIdx.x;   // < 81920
    const int hw  = idx & 1023;
    const int f   = (idx >> 10) % NF;
    const int t   = idx / (NF * 1024);
    const int n   = t * 1024 + hw;
    float s = 0.f;
#pragma unroll
    for (int c = 0; c < M_CHUNKS; c++)
        s += g_part[(size_t)c * (N_TOK * NF) + n * NF + f];
    out[idx] = s;
}

extern "C" void kernel_launch(void* const* d_in, const int* in_sizes, int n_in,
                              void* d_out, int out_size)
{
    const float* in1 = (const float*)d_in[0];
    const float* in2 = (const float*)d_in[1];
    const float* w1  = (const float*)d_in[2];
    const float* b1  = (const float*)d_in[3];
    const float* w2  = (const float*)d_in[4];
    const float* b2  = (const float*)d_in[5];
    const float* w3  = (const float*)d_in[6];
    const float* b3  = (const float*)d_in[7];

    dim3 pgrid(N_TOK / 64, 3);
    proj_kernel<<<pgrid, 256>>>(in1, in2, w1, b1, w2, b2, w3, b3);

    dim3 agrid(N_TOK / ROWS_PER_BLOCK, M_CHUNKS);
    attn_kernel<<<agrid, ATTN_THREADS>>>();

    reduce_kernel<<<(N_TOK * NF) / 256, 256>>>((float*)d_out);
}

// round 5
// speedup vs baseline: 1.8513x; 1.8513x over previous
#include <cuda_runtime.h>
#include <cuda_bf16.h>
#include <cstdint>

// Problem constants: B=1, T=8, C=64, H=W=32 -> N=8192 tokens, F=10
#define N_TOK 8192
#define NF 10
#define C_DIM 64
#define NT_TILES 64                    // m-tiles of 128
#define M_SPLIT 4
#define TILES_PER_CTA (NT_TILES / M_SPLIT)   // 16

// ---------------- device scratch (static; zero-init covers all pad slots) ----------------
__device__ uint32_t g_qs[N_TOK * 16];            // Q split rows: 32 bf16 (k=3f:[qh,qh,ql], 30,31=0)
__device__ uint32_t g_kc[NT_TILES * 128 * 16];   // K tiles: [tile][m][32 bf16] (k=3f:[kh,kl,kh])
__device__ uint32_t g_vc[NT_TILES * 2 * 16 * 64];// V tiles: [tile][hi|lo][f(16)][128 bf16 over m]
__device__ float    g_part[M_SPLIT * N_TOK * NF];

// ---------------- helpers ----------------
__device__ __forceinline__ void mma16816(float& d0, float& d1, float& d2, float& d3,
                                         uint32_t a0, uint32_t a1, uint32_t a2, uint32_t a3,
                                         uint32_t b0, uint32_t b1) {
    asm volatile("mma.sync.aligned.m16n8k16.row.col.f32.bf16.bf16.f32 "
                 "{%0,%1,%2,%3}, {%4,%5,%6,%7}, {%8,%9}, {%0,%1,%2,%3};"
                 : "+f"(d0), "+f"(d1), "+f"(d2), "+f"(d3)
                 : "r"(a0), "r"(a1), "r"(a2), "r"(a3), "r"(b0), "r"(b1));
}
__device__ __forceinline__ uint32_t packbf(float lo, float hi) {
    uint32_t r;   // first src -> upper half
    asm("cvt.rn.bf16x2.f32 %0, %1, %2;" : "=r"(r) : "f"(hi), "f"(lo));
    return r;
}
__device__ __forceinline__ float lo_f(uint32_t p) { return __uint_as_float(p << 16); }
__device__ __forceinline__ float hi_f(uint32_t p) { return __uint_as_float(p & 0xFFFF0000u); }
__device__ __forceinline__ void cp16(uint32_t saddr, const void* g) {
    asm volatile("cp.async.cg.shared.global [%0], [%1], 16;" :: "r"(saddr), "l"(g));
}
#define CP_COMMIT() asm volatile("cp.async.commit_group;" ::: "memory")
#define CP_WAIT(n)  asm volatile("cp.async.wait_group %0;" :: "n"(n) : "memory")

// ---------------- Kernel 1: projections -> split-bf16 operand images ----------------
// which==0: q and v from in1 (w1,b1 / w3,b3).  which==1: k from in2 (w2,b2).
__global__ __launch_bounds__(256) void proj_kernel(
    const float* __restrict__ in1, const float* __restrict__ in2,
    const float* __restrict__ w1, const float* __restrict__ b1,
    const float* __restrict__ w2, const float* __restrict__ b2,
    const float* __restrict__ w3, const float* __restrict__ b3)
{
    __shared__ float ws[2 * NF * C_DIM];          // up to two weight sets
    __shared__ float red[4 * 64 * 2 * NF];        // 4 parts x 64 tokens x <=20 feats

    const int which = blockIdx.y;                 // 0 = q+v, 1 = k
    const int nf    = (which == 0) ? 2 * NF : NF;
    const int tid   = threadIdx.x;

    if (which == 0) {
        for (int i = tid; i < NF * C_DIM; i += 256) {
            ws[i] = w1[i];
            ws[NF * C_DIM + i] = w3[i];
        }
    } else {
        for (int i = tid; i < NF * C_DIM; i += 256) ws[i] = w2[i];
    }
    __syncthreads();

    const int part = tid >> 6;
    const int ln   = tid & 63;
    const int n    = blockIdx.x * 64 + ln;
    const int t    = n >> 10;
    const int hw   = n & 1023;
    const float* xp = ((which == 0) ? in1 : in2) + t * (C_DIM * 1024) + hw;
    const int c0 = part * 16;

    float acc[2 * NF];
#pragma unroll
    for (int j = 0; j < 2 * NF; j++) acc[j] = 0.f;

    if (which == 0) {
#pragma unroll
        for (int cc = 0; cc < 16; cc++) {
            const int c = c0 + cc;
            float a = xp[c << 10];
#pragma unroll
            for (int f = 0; f < NF; f++) {
                acc[f]      = fmaf(ws[f * C_DIM + c], a, acc[f]);
                acc[NF + f] = fmaf(ws[NF * C_DIM + f * C_DIM + c], a, acc[NF + f]);
            }
        }
    } else {
#pragma unroll
        for (int cc = 0; cc < 16; cc++) {
            const int c = c0 + cc;
            float a = xp[c << 10];
#pragma unroll
            for (int f = 0; f < NF; f++)
                acc[f] = fmaf(ws[f * C_DIM + c], a, acc[f]);
        }
    }
#pragma unroll
    for (int j = 0; j < 2 * NF; j++)
        if (j < nf) red[part * (64 * 2 * NF) + ln * (2 * NF) + j] = acc[j];
    __syncthreads();

    uint16_t* qs = reinterpret_cast<uint16_t*>(g_qs);
    uint16_t* kc = reinterpret_cast<uint16_t*>(g_kc);
    uint16_t* vc = reinterpret_cast<uint16_t*>(g_vc);

    for (int idx = tid; idx < 64 * nf; idx += 256) {
        const int ln2 = idx / nf;
        const int j   = idx % nf;
        const int jj  = ln2 * (2 * NF) + j;
        const int nn  = blockIdx.x * 64 + ln2;
        float s = red[jj] + red[64 * 2 * NF + jj] + red[2 * 64 * 2 * NF + jj]
                + red[3 * 64 * 2 * NF + jj];
        const int tile = nn >> 7;
        const int m    = nn & 127;
        if (which == 1) {
            // k
            s += __ldg(b2 + j);
            __nv_bfloat16 hb = __float2bfloat16(s);
            __nv_bfloat16 lb = __float2bfloat16(s - __bfloat162float(hb));
            uint16_t h = __bfloat16_as_ushort(hb), l = __bfloat16_as_ushort(lb);
            uint16_t* row = kc + (size_t)(tile * 128 + m) * 32;
            row[3 * j]     = h;
            row[3 * j + 1] = l;
            row[3 * j + 2] = h;
        } else if (j < NF) {
            // q
            float sq = s + __ldg(b1 + j);
            __nv_bfloat16 hb = __float2bfloat16(sq);
            __nv_bfloat16 lb = __float2bfloat16(sq - __bfloat162float(hb));
            uint16_t h = __bfloat16_as_ushort(hb), l = __bfloat16_as_ushort(lb);
            uint16_t* row = qs + (size_t)nn * 32;
            row[3 * j]     = h;
            row[3 * j + 1] = h;
            row[3 * j + 2] = l;
        } else {
            // v
            const int f = j - NF;
            float sv = s + __ldg(b3 + f);
            __nv_bfloat16 hb = __float2bfloat16(sv);
            __nv_bfloat16 lb = __float2bfloat16(sv - __bfloat162float(hb));
            vc[(size_t)tile * 4096 + 0 * 2048 + f * 128 + m] = __bfloat16_as_ushort(hb);
            vc[(size_t)tile * 4096 + 1 * 2048 + f * 128 + m] = __bfloat16_as_ushort(lb);
        }
    }
}

// ---------------- Kernel 2: mma.sync flash relu-attention ----------------
// Block: 256 thr (8 warps), 128 q-rows; loops 16 m-tiles (M_SPLIT=4 chunk).
// MMA1: S[16,128] per warp = Qsplit(k=32) x Ksplit^T, fp32 accum.
// relu + exact bf16 hi/lo split in registers (D-frag == A-frag layout).
// MMA2: O[16,16] += Sh*Vh + Sh*Vl + Sl*Vh  (3 x k=128 per tile).
__global__ __launch_bounds__(256, 2) void attn_kernel()
{
    __shared__ __align__(16) uint32_t sK[2][128 * 20];    // padded stride 20 words
    __shared__ __align__(16) uint32_t sV[2][2 * 16 * 68]; // padded stride 68 words

    const int tid  = threadIdx.x;
    const int wid  = tid >> 5;
    const int lane = tid & 31;
    const int n0   = blockIdx.x * 128;
    const int my   = blockIdx.y;
    const int t0   = my * TILES_PER_CTA;

    // ---- Q A-fragments (persistent): rows rq, rq+8, k=0..31 ----
    const int rq = n0 + wid * 16 + (lane >> 2);
    const int l4 = lane & 3;
    uint32_t a_q[8];
    a_q[0] = g_qs[rq * 16 + l4];
    a_q[1] = g_qs[(rq + 8) * 16 + l4];
    a_q[2] = g_qs[rq * 16 + l4 + 4];
    a_q[3] = g_qs[(rq + 8) * 16 + l4 + 4];
    a_q[4] = g_qs[rq * 16 + l4 + 8];
    a_q[5] = g_qs[(rq + 8) * 16 + l4 + 8];
    a_q[6] = g_qs[rq * 16 + l4 + 12];
    a_q[7] = g_qs[(rq + 8) * 16 + l4 + 12];

    float O0[4] = {0.f, 0.f, 0.f, 0.f};
    float O1[4] = {0.f, 0.f, 0.f, 0.f};

    // ---- staging lambda ----
    auto stage = [&](int buf, int tile) {
        const char* kbase = reinterpret_cast<const char*>(g_kc) + (size_t)tile * 8192;
        const char* vbase = reinterpret_cast<const char*>(g_vc) + (size_t)tile * 8192;
#pragma unroll
        for (int c = tid; c < 512; c += 256) {
            int m = c >> 2, w4 = c & 3;
            uint32_t sa = (uint32_t)__cvta_generic_to_shared(&sK[buf][m * 20 + w4 * 4]);
            cp16(sa, kbase + c * 16);
        }
#pragma unroll
        for (int c = tid; c < 512; c += 256) {
            int sel = c >> 8, rest = c & 255;
            int f = rest >> 4, w4 = rest & 15;
            uint32_t sa = (uint32_t)__cvta_generic_to_shared(&sV[buf][(sel * 16 + f) * 68 + w4 * 4]);
            cp16(sa, vbase + c * 16);
        }
    };

    stage(0, t0);
    CP_COMMIT();

    for (int i = 0; i < TILES_PER_CTA; i++) {
        if (i + 1 < TILES_PER_CTA) {
            stage((i + 1) & 1, t0 + i + 1);
            CP_COMMIT();
            CP_WAIT(1);
        } else {
            CP_WAIT(0);
        }
        __syncthreads();

        const int buf = i & 1;

        // ---- MMA1: D[16 n-steps][4] ----
        float D[16][4];
#pragma unroll
        for (int ns = 0; ns < 16; ns++) {
            float d0 = 0.f, d1 = 0.f, d2 = 0.f, d3 = 0.f;
            const int mcol = ns * 8 + (lane >> 2);
            const uint32_t* kr = &sK[buf][mcol * 20 + l4];
            uint32_t b0 = kr[0], b1 = kr[4];
            mma16816(d0, d1, d2, d3, a_q[0], a_q[1], a_q[2], a_q[3], b0, b1);
            uint32_t b2 = kr[8], b3 = kr[12];
            mma16816(d0, d1, d2, d3, a_q[4], a_q[5], a_q[6], a_q[7], b2, b3);
            D[ns][0] = d0; D[ns][1] = d1; D[ns][2] = d2; D[ns][3] = d3;
        }

        // ---- relu + split + MMA2 (register-resident A fragments) ----
        const uint32_t* vb = &sV[buf][0];
        const int fr = lane >> 2;
#pragma unroll
        for (int kb = 0; kb < 8; kb++) {
            float c0 = fmaxf(D[2 * kb][0], 0.f), c1 = fmaxf(D[2 * kb][1], 0.f);
            float c2 = fmaxf(D[2 * kb][2], 0.f), c3 = fmaxf(D[2 * kb][3], 0.f);
            float e0 = fmaxf(D[2 * kb + 1][0], 0.f), e1 = fmaxf(D[2 * kb + 1][1], 0.f);
            float e2 = fmaxf(D[2 * kb + 1][2], 0.f), e3 = fmaxf(D[2 * kb + 1][3], 0.f);

            uint32_t sh0 = packbf(c0, c1), sh1 = packbf(c2, c3);
            uint32_t sh2 = packbf(e0, e1), sh3 = packbf(e2, e3);
            uint32_t sl0 = packbf(c0 - lo_f(sh0), c1 - hi_f(sh0));
            uint32_t sl1 = packbf(c2 - lo_f(sh1), c3 - hi_f(sh1));
            uint32_t sl2 = packbf(e0 - lo_f(sh2), e1 - hi_f(sh2));
            uint32_t sl3 = packbf(e2 - lo_f(sh3), e3 - hi_f(sh3));

            const int wk = kb * 8 + l4;
            uint32_t vh0 = vb[fr * 68 + wk],        vh1 = vb[fr * 68 + wk + 4];
            uint32_t vl0 = vb[(16 + fr) * 68 + wk], vl1 = vb[(16 + fr) * 68 + wk + 4];
            uint32_t wh0 = vb[(8 + fr) * 68 + wk],  wh1 = vb[(8 + fr) * 68 + wk + 4];
            uint32_t wl0 = vb[(24 + fr) * 68 + wk], wl1 = vb[(24 + fr) * 68 + wk + 4];

            mma16816(O0[0], O0[1], O0[2], O0[3], sh0, sh1, sh2, sh3, vh0, vh1);
            mma16816(O0[0], O0[1], O0[2], O0[3], sh0, sh1, sh2, sh3, vl0, vl1);
            mma16816(O0[0], O0[1], O0[2], O0[3], sl0, sl1, sl2, sl3, vh0, vh1);

            mma16816(O1[0], O1[1], O1[2], O1[3], sh0, sh1, sh2, sh3, wh0, wh1);
            mma16816(O1[0], O1[1], O1[2], O1[3], sh0, sh1, sh2, sh3, wl0, wl1);
            mma16816(O1[0], O1[1], O1[2], O1[3], sl0, sl1, sl2, sl3, wh0, wh1);
        }
        __syncthreads();
    }

    // ---- epilogue: O fragments -> g_part[my] ----
    {
        float* po = g_part + (size_t)my * (N_TOK * NF);
        const int r0 = rq;          // row for c0,c1 ; r0+8 for c2,c3
        const int f0 = l4 * 2;      // 0,2,4,6
        po[(size_t)r0 * NF + f0]           = O0[0];
        po[(size_t)r0 * NF + f0 + 1]       = O0[1];
        po[(size_t)(r0 + 8) * NF + f0]     = O0[2];
        po[(size_t)(r0 + 8) * NF + f0 + 1] = O0[3];
        if (l4 == 0) {              // f = 8,9
            po[(size_t)r0 * NF + 8]       = O1[0];
            po[(size_t)r0 * NF + 9]       = O1[1];
            po[(size_t)(r0 + 8) * NF + 8] = O1[2];
            po[(size_t)(r0 + 8) * NF + 9] = O1[3];
        }
    }
}

// ---------------- Kernel 3: deterministic reduce + output permute ----------------
__global__ __launch_bounds__(256) void reduce_kernel(float* __restrict__ out)
{
    const int idx = blockIdx.x * blockDim.x + threadIdx.x;   // < 81920
    const int hw  = idx & 1023;
    const int f   = (idx >> 10) % NF;
    const int t   = idx / (NF * 1024);
    const int n   = t * 1024 + hw;
    float s = 0.f;
#pragma unroll
    for (int c = 0; c < M_SPLIT; c++)
        s += g_part[(size_t)c * (N_TOK * NF) + n * NF + f];
    out[idx] = s;
}

extern "C" void kernel_launch(void* const* d_in, const int* in_sizes, int n_in,
                              void* d_out, int out_size)
{
    const float* in1 = (const float*)d_in[0];
    const float* in2 = (const float*)d_in[1];
    const float* w1  = (const float*)d_in[2];
    const float* b1  = (const float*)d_in[3];
    const float* w2  = (const float*)d_in[4];
    const float* b2  = (const float*)d_in[5];
    const float* w3  = (const float*)d_in[6];
    const float* b3  = (const float*)d_in[7];

    dim3 pgrid(N_TOK / 64, 2);
    proj_kernel<<<pgrid, 256>>>(in1, in2, w1, b1, w2, b2, w3, b3);

    dim3 agrid(N_TOK / 128, M_SPLIT);
    attn_kernel<<<agrid, 256>>>();

    reduce_kernel<<<(N_TOK * NF) / 256, 256>>>((float*)d_out);
}

// round 6
// speedup vs baseline: 1.9409x; 1.0484x over previous
#include <cuda_runtime.h>
#include <cuda_bf16.h>
#include <cstdint>

// Problem constants: B=1, T=8, C=64, H=W=32 -> N=8192 tokens, F=10
#define N_TOK 8192
#define NF 10
#define C_DIM 64
#define NT_TILES 64                    // m-tiles of 128
#define M_SPLIT 4
#define TILES_PER_CTA (NT_TILES / M_SPLIT)   // 16

// ---------------- device scratch (static; zero-init covers all pad slots) ----------------
__device__ uint32_t g_qs[N_TOK * 16];            // Q split rows: 32 bf16 (k=3f:[qh,qh,ql], 30,31=0)
__device__ uint32_t g_kc[NT_TILES * 128 * 16];   // K tiles: [tile][m][32 bf16] (k=3f:[kh,kl,kh])
__device__ uint32_t g_vc[NT_TILES * 2 * 16 * 64];// V tiles: [tile][hi|lo][f(16)][128 bf16 over m]
__device__ float    g_part[M_SPLIT * N_TOK * NF];

// ---------------- helpers ----------------
__device__ __forceinline__ void mma16816(float& d0, float& d1, float& d2, float& d3,
                                         uint32_t a0, uint32_t a1, uint32_t a2, uint32_t a3,
                                         uint32_t b0, uint32_t b1) {
    asm volatile("mma.sync.aligned.m16n8k16.row.col.f32.bf16.bf16.f32 "
                 "{%0,%1,%2,%3}, {%4,%5,%6,%7}, {%8,%9}, {%0,%1,%2,%3};"
                 : "+f"(d0), "+f"(d1), "+f"(d2), "+f"(d3)
                 : "r"(a0), "r"(a1), "r"(a2), "r"(a3), "r"(b0), "r"(b1));
}
__device__ __forceinline__ void ldsm4(uint32_t& r0, uint32_t& r1, uint32_t& r2, uint32_t& r3,
                                      uint32_t addr) {
    asm volatile("ldmatrix.sync.aligned.m8n8.x4.shared.b16 {%0,%1,%2,%3}, [%4];"
                 : "=r"(r0), "=r"(r1), "=r"(r2), "=r"(r3) : "r"(addr));
}
__device__ __forceinline__ uint32_t packbf(float lo, float hi) {
    uint32_t r;   // first src -> upper half
    asm("cvt.rn.bf16x2.f32 %0, %1, %2;" : "=r"(r) : "f"(hi), "f"(lo));
    return r;
}
__device__ __forceinline__ float lo_f(uint32_t p) { return __uint_as_float(p << 16); }
__device__ __forceinline__ float hi_f(uint32_t p) { return __uint_as_float(p & 0xFFFF0000u); }
__device__ __forceinline__ void cp16(uint32_t saddr, const void* g) {
    asm volatile("cp.async.cg.shared.global [%0], [%1], 16;" :: "r"(saddr), "l"(g));
}
#define CP_COMMIT() asm volatile("cp.async.commit_group;" ::: "memory")
#define CP_WAIT(n)  asm volatile("cp.async.wait_group %0;" :: "n"(n) : "memory")

// ---------------- Kernel 1: projections -> split-bf16 operand images ----------------
// which: 0=q (in1,w1,b1), 1=k (in2,w2,b2), 2=v (in1,w3,b3). 8-way c-split, 32 tokens/block.
__global__ __launch_bounds__(256) void proj_kernel(
    const float* __restrict__ in1, const float* __restrict__ in2,
    const float* __restrict__ w1, const float* __restrict__ b1,
    const float* __restrict__ w2, const float* __restrict__ b2,
    const float* __restrict__ w3, const float* __restrict__ b3)
{
    __shared__ float ws[NF * C_DIM];
    __shared__ float red[8 * 32 * NF];

    const int which = blockIdx.y;
    const float* w    = (which == 0) ? w1 : (which == 1) ? w2 : w3;
    const float* bias = (which == 0) ? b1 : (which == 1) ? b2 : b3;
    const float* x    = (which == 1) ? in2 : in1;

    const int tid = threadIdx.x;
    for (int i = tid; i < NF * C_DIM; i += 256) ws[i] = w[i];
    __syncthreads();

    const int part = tid >> 5;                // 0..7 (warp-uniform)
    const int ln   = tid & 31;
    const int n    = blockIdx.x * 32 + ln;
    const int t    = n >> 10;
    const int hw   = n & 1023;
    const float* xp = x + t * (C_DIM * 1024) + hw;
    const int c0 = part * 8;

    float acc[NF];
#pragma unroll
    for (int f = 0; f < NF; f++) acc[f] = 0.f;
#pragma unroll
    for (int cc = 0; cc < 8; cc++) {
        const int c = c0 + cc;
        float a = xp[c << 10];
#pragma unroll
        for (int f = 0; f < NF; f++)
            acc[f] = fmaf(ws[f * C_DIM + c], a, acc[f]);
    }
#pragma unroll
    for (int f = 0; f < NF; f++)
        red[part * (32 * NF) + ln * NF + f] = acc[f];
    __syncthreads();

    uint16_t* qs = reinterpret_cast<uint16_t*>(g_qs);
    uint16_t* kc = reinterpret_cast<uint16_t*>(g_kc);
    uint16_t* vc = reinterpret_cast<uint16_t*>(g_vc);

    for (int idx = tid; idx < 32 * NF; idx += 256) {
        const int ln2 = idx / NF;
        const int f   = idx % NF;
        const int nn  = blockIdx.x * 32 + ln2;
        float s = 0.f;
#pragma unroll
        for (int p = 0; p < 8; p++) s += red[p * (32 * NF) + idx];
        s += __ldg(bias + f);

        __nv_bfloat16 hb = __float2bfloat16(s);
        __nv_bfloat16 lb = __float2bfloat16(s - __bfloat162float(hb));
        uint16_t h = __bfloat16_as_ushort(hb), l = __bfloat16_as_ushort(lb);
        const int tile = nn >> 7;
        const int m    = nn & 127;

        if (which == 0) {
            uint16_t* row = qs + (size_t)nn * 32;
            row[3 * f] = h; row[3 * f + 1] = h; row[3 * f + 2] = l;
        } else if (which == 1) {
            uint16_t* row = kc + (size_t)(tile * 128 + m) * 32;
            row[3 * f] = h; row[3 * f + 1] = l; row[3 * f + 2] = h;
        } else {
            vc[(size_t)tile * 4096 + 0 * 2048 + f * 128 + m] = h;
            vc[(size_t)tile * 4096 + 1 * 2048 + f * 128 + m] = l;
        }
    }
}

// ---------------- Kernel 2: mma.sync flash relu-attention (ldmatrix B-frags) ----------------
__global__ __launch_bounds__(256, 2) void attn_kernel()
{
    __shared__ __align__(16) uint32_t sK[2][128 * 20];    // padded stride 20 words
    __shared__ __align__(16) uint32_t sV[2][2 * 16 * 68]; // padded stride 68 words

    const int tid  = threadIdx.x;
    const int wid  = tid >> 5;
    const int lane = tid & 31;
    const int n0   = blockIdx.x * 128;
    const int my   = blockIdx.y;
    const int t0   = my * TILES_PER_CTA;

    // ---- Q A-fragments (persistent) ----
    const int rq = n0 + wid * 16 + (lane >> 2);
    const int l4 = lane & 3;
    uint32_t a_q[8];
    a_q[0] = g_qs[rq * 16 + l4];
    a_q[1] = g_qs[(rq + 8) * 16 + l4];
    a_q[2] = g_qs[rq * 16 + l4 + 4];
    a_q[3] = g_qs[(rq + 8) * 16 + l4 + 4];
    a_q[4] = g_qs[rq * 16 + l4 + 8];
    a_q[5] = g_qs[(rq + 8) * 16 + l4 + 8];
    a_q[6] = g_qs[rq * 16 + l4 + 12];
    a_q[7] = g_qs[(rq + 8) * 16 + l4 + 12];

    float O0[4] = {0.f, 0.f, 0.f, 0.f};
    float O1[4] = {0.f, 0.f, 0.f, 0.f};

    // ldmatrix lane-address components (word offsets within a buffer)
    const uint32_t kRowOff = (uint32_t)((lane & 7) * 20 + (lane >> 3) * 4);          // MMA1
    const int frow = (lane & 7) + ((lane >> 4) << 3);                                 // MMA2 f-row
    const uint32_t vRowOff = (uint32_t)(frow * 68 + ((lane >> 3) & 1) * 4);           // MMA2

    auto stage = [&](int buf, int tile) {
        const char* kbase = reinterpret_cast<const char*>(g_kc) + (size_t)tile * 8192;
        const char* vbase = reinterpret_cast<const char*>(g_vc) + (size_t)tile * 8192;
#pragma unroll
        for (int c = tid; c < 512; c += 256) {
            int m = c >> 2, w4 = c & 3;
            uint32_t sa = (uint32_t)__cvta_generic_to_shared(&sK[buf][m * 20 + w4 * 4]);
            cp16(sa, kbase + c * 16);
        }
#pragma unroll
        for (int c = tid; c < 512; c += 256) {
            int sel = c >> 8, rest = c & 255;
            int f = rest >> 4, w4 = rest & 15;
            uint32_t sa = (uint32_t)__cvta_generic_to_shared(&sV[buf][(sel * 16 + f) * 68 + w4 * 4]);
            cp16(sa, vbase + c * 16);
        }
    };

    stage(0, t0);
    CP_COMMIT();

    for (int i = 0; i < TILES_PER_CTA; i++) {
        if (i + 1 < TILES_PER_CTA) {
            stage((i + 1) & 1, t0 + i + 1);
            CP_COMMIT();
            CP_WAIT(1);
        } else {
            CP_WAIT(0);
        }
        __syncthreads();

        const int buf = i & 1;
        const uint32_t kBase = (uint32_t)__cvta_generic_to_shared(&sK[buf][0]) + kRowOff * 4;
        const uint32_t vBaseH = (uint32_t)__cvta_generic_to_shared(&sV[buf][0]) + vRowOff * 4;
        const uint32_t vBaseL = vBaseH + 16 * 68 * 4;

        // ---- MMA1: D[16 n-steps][4] ----
        float D[16][4];
#pragma unroll
        for (int ns = 0; ns < 16; ns++) {
            uint32_t b0, b1, b2, b3;
            ldsm4(b0, b1, b2, b3, kBase + (uint32_t)ns * 640);   // 8 rows * 80B
            float d0 = 0.f, d1 = 0.f, d2 = 0.f, d3 = 0.f;
            mma16816(d0, d1, d2, d3, a_q[0], a_q[1], a_q[2], a_q[3], b0, b1);
            mma16816(d0, d1, d2, d3, a_q[4], a_q[5], a_q[6], a_q[7], b2, b3);
            D[ns][0] = d0; D[ns][1] = d1; D[ns][2] = d2; D[ns][3] = d3;
        }

        // ---- relu + split + MMA2 ----
#pragma unroll
        for (int kb = 0; kb < 8; kb++) {
            float c0 = fmaxf(D[2 * kb][0], 0.f), c1 = fmaxf(D[2 * kb][1], 0.f);
            float c2 = fmaxf(D[2 * kb][2], 0.f), c3 = fmaxf(D[2 * kb][3], 0.f);
            float e0 = fmaxf(D[2 * kb + 1][0], 0.f), e1 = fmaxf(D[2 * kb + 1][1], 0.f);
            float e2 = fmaxf(D[2 * kb + 1][2], 0.f), e3 = fmaxf(D[2 * kb + 1][3], 0.f);

            uint32_t sh0 = packbf(c0, c1), sh1 = packbf(c2, c3);
            uint32_t sh2 = packbf(e0, e1), sh3 = packbf(e2, e3);
            uint32_t sl0 = packbf(c0 - lo_f(sh0), c1 - hi_f(sh0));
            uint32_t sl1 = packbf(c2 - lo_f(sh1), c3 - hi_f(sh1));
            uint32_t sl2 = packbf(e0 - lo_f(sh2), e1 - hi_f(sh2));
            uint32_t sl3 = packbf(e2 - lo_f(sh3), e3 - hi_f(sh3));

            uint32_t vh0, vh1, wh0, wh1, vl0, vl1, wl0, wl1;
            ldsm4(vh0, vh1, wh0, wh1, vBaseH + (uint32_t)kb * 32);
            ldsm4(vl0, vl1, wl0, wl1, vBaseL + (uint32_t)kb * 32);

            mma16816(O0[0], O0[1], O0[2], O0[3], sh0, sh1, sh2, sh3, vh0, vh1);
            mma16816(O0[0], O0[1], O0[2], O0[3], sh0, sh1, sh2, sh3, vl0, vl1);
            mma16816(O0[0], O0[1], O0[2], O0[3], sl0, sl1, sl2, sl3, vh0, vh1);

            mma16816(O1[0], O1[1], O1[2], O1[3], sh0, sh1, sh2, sh3, wh0, wh1);
            mma16816(O1[0], O1[1], O1[2], O1[3], sh0, sh1, sh2, sh3, wl0, wl1);
            mma16816(O1[0], O1[1], O1[2], O1[3], sl0, sl1, sl2, sl3, wh0, wh1);
        }
        __syncthreads();
    }

    // ---- epilogue ----
    {
        float* po = g_part + (size_t)my * (N_TOK * NF);
        const int r0 = rq;
        const int f0 = l4 * 2;
        po[(size_t)r0 * NF + f0]           = O0[0];
        po[(size_t)r0 * NF + f0 + 1]       = O0[1];
        po[(size_t)(r0 + 8) * NF + f0]     = O0[2];
        po[(size_t)(r0 + 8) * NF + f0 + 1] = O0[3];
        if (l4 == 0) {
            po[(size_t)r0 * NF + 8]       = O1[0];
            po[(size_t)r0 * NF + 9]       = O1[1];
            po[(size_t)(r0 + 8) * NF + 8] = O1[2];
            po[(size_t)(r0 + 8) * NF + 9] = O1[3];
        }
    }
}

// ---------------- Kernel 3: deterministic reduce + output permute ----------------
__global__ __launch_bounds__(256) void reduce_kernel(float* __restrict__ out)
{
    const int idx = blockIdx.x * blockDim.x + threadIdx.x;   // < 81920
    const int hw  = idx & 1023;
    const int f   = (idx >> 10) % NF;
    const int t   = idx / (NF * 1024);
    const int n   = t * 1024 + hw;
    float s = 0.f;
#pragma unroll
    for (int c = 0; c < M_SPLIT; c++)
        s += g_part[(size_t)c * (N_TOK * NF) + n * NF + f];
    out[idx] = s;
}

extern "C" void kernel_launch(void* const* d_in, const int* in_sizes, int n_in,
                              void* d_out, int out_size)
{
    const float* in1 = (const float*)d_in[0];
    const float* in2 = (const float*)d_in[1];
    const float* w1  = (const float*)d_in[2];
    const float* b1  = (const float*)d_in[3];
    const float* w2  = (const float*)d_in[4];
    const float* b2  = (const float*)d_in[5];
    const float* w3  = (const float*)d_in[6];
    const float* b3  = (const float*)d_in[7];

    dim3 pgrid(N_TOK / 32, 3);
    proj_kernel<<<pgrid, 256>>>(in1, in2, w1, b1, w2, b2, w3, b3);

    dim3 agrid(N_TOK / 128, M_SPLIT);
    attn_kernel<<<agrid, 256>>>();

    reduce_kernel<<<(N_TOK * NF) / 256, 256>>>((float*)d_out);
}

// round 7
// speedup vs baseline: 2.3442x; 1.2078x over previous
#include <cuda_runtime.h>
#include <cuda_bf16.h>
#include <cuda_fp16.h>
#include <cstdint>

// Problem constants: B=1, T=8, C=64, H=W=32 -> N=8192 tokens, F=10
#define N_TOK 8192
#define NF 10
#define C_DIM 64
#define NT_TILES 64                    // m-tiles of 128
#define M_SPLIT 4
#define TILES_PER_CTA (NT_TILES / M_SPLIT)   // 16

// ---------------- device scratch (static; zero-init covers all pad slots) ----------------
__device__ uint32_t g_qs[N_TOK * 16];            // Q split rows: 32 bf16 (k=3f:[qh,qh,ql], 30,31=0)
__device__ uint32_t g_kc[NT_TILES * 128 * 16];   // K tiles: [tile][m][32 bf16] (k=3f:[kh,kl,kh])
__device__ uint32_t g_vc[NT_TILES * 2 * 16 * 64];// V tiles: [tile][hi|lo][f(16)][128 fp16 over m]
__device__ float    g_part[M_SPLIT * N_TOK * NF];

// ---------------- helpers ----------------
__device__ __forceinline__ void mma_bf16(float& d0, float& d1, float& d2, float& d3,
                                         uint32_t a0, uint32_t a1, uint32_t a2, uint32_t a3,
                                         uint32_t b0, uint32_t b1) {
    asm volatile("mma.sync.aligned.m16n8k16.row.col.f32.bf16.bf16.f32 "
                 "{%0,%1,%2,%3}, {%4,%5,%6,%7}, {%8,%9}, {%0,%1,%2,%3};"
                 : "+f"(d0), "+f"(d1), "+f"(d2), "+f"(d3)
                 : "r"(a0), "r"(a1), "r"(a2), "r"(a3), "r"(b0), "r"(b1));
}
__device__ __forceinline__ void mma_f16(float* o,
                                        uint32_t a0, uint32_t a1, uint32_t a2, uint32_t a3,
                                        uint32_t b0, uint32_t b1) {
    asm volatile("mma.sync.aligned.m16n8k16.row.col.f32.f16.f16.f32 "
                 "{%0,%1,%2,%3}, {%4,%5,%6,%7}, {%8,%9}, {%0,%1,%2,%3};"
                 : "+f"(o[0]), "+f"(o[1]), "+f"(o[2]), "+f"(o[3])
                 : "r"(a0), "r"(a1), "r"(a2), "r"(a3), "r"(b0), "r"(b1));
}
__device__ __forceinline__ void ldsm4(uint32_t& r0, uint32_t& r1, uint32_t& r2, uint32_t& r3,
                                      uint32_t addr) {
    asm volatile("ldmatrix.sync.aligned.m8n8.x4.shared.b16 {%0,%1,%2,%3}, [%4];"
                 : "=r"(r0), "=r"(r1), "=r"(r2), "=r"(r3) : "r"(addr));
}
__device__ __forceinline__ uint32_t packh(float lo, float hi) {
    uint32_t r;   // first src -> upper half
    asm("cvt.rn.f16x2.f32 %0, %1, %2;" : "=r"(r) : "f"(hi), "f"(lo));
    return r;
}
__device__ __forceinline__ void cp16(uint32_t saddr, const void* g) {
    asm volatile("cp.async.cg.shared.global [%0], [%1], 16;" :: "r"(saddr), "l"(g));
}
#define CP_COMMIT() asm volatile("cp.async.commit_group;" ::: "memory")
#define CP_WAIT(n)  asm volatile("cp.async.wait_group %0;" :: "n"(n) : "memory")

// ---------------- Kernel 1: projections -> split operand images ----------------
// which: 0=q (in1,w1,b1), 1=k (in2,w2,b2), 2=v (in1,w3,b3). 4-way c-split, 64 tokens/block.
__global__ __launch_bounds__(256) void proj_kernel(
    const float* __restrict__ in1, const float* __restrict__ in2,
    const float* __restrict__ w1, const float* __restrict__ b1,
    const float* __restrict__ w2, const float* __restrict__ b2,
    const float* __restrict__ w3, const float* __restrict__ b3)
{
    __shared__ float ws[NF * C_DIM];
    __shared__ float red[4 * 64 * NF];

    const int which = blockIdx.y;
    const float* w    = (which == 0) ? w1 : (which == 1) ? w2 : w3;
    const float* bias = (which == 0) ? b1 : (which == 1) ? b2 : b3;
    const float* x    = (which == 1) ? in2 : in1;

    const int tid = threadIdx.x;
    for (int i = tid; i < NF * C_DIM; i += 256) ws[i] = w[i];
    __syncthreads();

    const int part = tid >> 6;                // 0..3 (warp-uniform)
    const int ln   = tid & 63;
    const int n    = blockIdx.x * 64 + ln;
    const int t    = n >> 10;
    const int hw   = n & 1023;
    const float* xp = x + t * (C_DIM * 1024) + hw;
    const int c0 = part * 16;

    float acc[NF];
#pragma unroll
    for (int f = 0; f < NF; f++) acc[f] = 0.f;
#pragma unroll
    for (int cc = 0; cc < 16; cc++) {
        const int c = c0 + cc;
        float a = xp[c << 10];
#pragma unroll
        for (int f = 0; f < NF; f++)
            acc[f] = fmaf(ws[f * C_DIM + c], a, acc[f]);
    }
#pragma unroll
    for (int f = 0; f < NF; f++)
        red[part * (64 * NF) + ln * NF + f] = acc[f];
    __syncthreads();

    uint16_t* qs = reinterpret_cast<uint16_t*>(g_qs);
    uint16_t* kc = reinterpret_cast<uint16_t*>(g_kc);
    uint16_t* vc = reinterpret_cast<uint16_t*>(g_vc);

    for (int idx = tid; idx < 64 * NF; idx += 256) {
        const int ln2 = idx / NF;
        const int f   = idx % NF;
        const int nn  = blockIdx.x * 64 + ln2;
        float s = red[idx] + red[64 * NF + idx] + red[2 * 64 * NF + idx]
                + red[3 * 64 * NF + idx] + __ldg(bias + f);

        const int tile = nn >> 7;
        const int m    = nn & 127;

        if (which == 0) {
            __nv_bfloat16 hb = __float2bfloat16(s);
            __nv_bfloat16 lb = __float2bfloat16(s - __bfloat162float(hb));
            uint16_t h = __bfloat16_as_ushort(hb), l = __bfloat16_as_ushort(lb);
            uint16_t* row = qs + (size_t)nn * 32;
            row[3 * f] = h; row[3 * f + 1] = h; row[3 * f + 2] = l;
        } else if (which == 1) {
            __nv_bfloat16 hb = __float2bfloat16(s);
            __nv_bfloat16 lb = __float2bfloat16(s - __bfloat162float(hb));
            uint16_t h = __bfloat16_as_ushort(hb), l = __bfloat16_as_ushort(lb);
            uint16_t* row = kc + (size_t)(tile * 128 + m) * 32;
            row[3 * f] = h; row[3 * f + 1] = l; row[3 * f + 2] = h;
        } else {
            // v in fp16 hi/lo split (exact to ~2^-22)
            __half hh = __float2half_rn(s);
            __half hl = __float2half_rn(s - __half2float(hh));
            vc[(size_t)tile * 4096 + 0 * 2048 + f * 128 + m] = __half_as_ushort(hh);
            vc[(size_t)tile * 4096 + 1 * 2048 + f * 128 + m] = __half_as_ushort(hl);
        }
    }
}

// ---------------- Kernel 2: mma.sync flash relu-attention ----------------
// MMA1: bf16 3-term split (exact to ~2^-17). MMA2: fp16 2-term (Sh fp16; V fp16 hi/lo).
__global__ __launch_bounds__(256, 2) void attn_kernel()
{
    __shared__ __align__(16) uint32_t sK[2][128 * 20];    // padded stride 20 words
    __shared__ __align__(16) uint32_t sV[2][2 * 16 * 68]; // padded stride 68 words

    const int tid  = threadIdx.x;
    const int wid  = tid >> 5;
    const int lane = tid & 31;
    const int n0   = blockIdx.x * 128;
    const int my   = blockIdx.y;
    const int t0   = my * TILES_PER_CTA;

    // ---- Q A-fragments (persistent) ----
    const int rq = n0 + wid * 16 + (lane >> 2);
    const int l4 = lane & 3;
    uint32_t a_q[8];
    a_q[0] = g_qs[rq * 16 + l4];
    a_q[1] = g_qs[(rq + 8) * 16 + l4];
    a_q[2] = g_qs[rq * 16 + l4 + 4];
    a_q[3] = g_qs[(rq + 8) * 16 + l4 + 4];
    a_q[4] = g_qs[rq * 16 + l4 + 8];
    a_q[5] = g_qs[(rq + 8) * 16 + l4 + 8];
    a_q[6] = g_qs[rq * 16 + l4 + 12];
    a_q[7] = g_qs[(rq + 8) * 16 + l4 + 12];

    float O0[4] = {0.f, 0.f, 0.f, 0.f};
    float O1[4] = {0.f, 0.f, 0.f, 0.f};

    // ldmatrix lane-address components (word offsets within a buffer)
    const uint32_t kRowOff = (uint32_t)((lane & 7) * 20 + (lane >> 3) * 4);          // MMA1
    const int frow = (lane & 7) + ((lane >> 4) << 3);                                 // MMA2 f-row
    const uint32_t vRowOff = (uint32_t)(frow * 68 + ((lane >> 3) & 1) * 4);           // MMA2

    auto stage = [&](int buf, int tile) {
        const char* kbase = reinterpret_cast<const char*>(g_kc) + (size_t)tile * 8192;
        const char* vbase = reinterpret_cast<const char*>(g_vc) + (size_t)tile * 8192;
#pragma unroll
        for (int c = tid; c < 512; c += 256) {
            int m = c >> 2, w4 = c & 3;
            uint32_t sa = (uint32_t)__cvta_generic_to_shared(&sK[buf][m * 20 + w4 * 4]);
            cp16(sa, kbase + c * 16);
        }
#pragma unroll
        for (int c = tid; c < 512; c += 256) {
            int sel = c >> 8, rest = c & 255;
            int f = rest >> 4, w4 = rest & 15;
            uint32_t sa = (uint32_t)__cvta_generic_to_shared(&sV[buf][(sel * 16 + f) * 68 + w4 * 4]);
            cp16(sa, vbase + c * 16);
        }
    };

    stage(0, t0);
    CP_COMMIT();

    for (int i = 0; i < TILES_PER_CTA; i++) {
        if (i + 1 < TILES_PER_CTA) {
            stage((i + 1) & 1, t0 + i + 1);
            CP_COMMIT();
            CP_WAIT(1);
        } else {
            CP_WAIT(0);
        }
        __syncthreads();

        const int buf = i & 1;
        const uint32_t kBase = (uint32_t)__cvta_generic_to_shared(&sK[buf][0]) + kRowOff * 4;
        const uint32_t vBaseH = (uint32_t)__cvta_generic_to_shared(&sV[buf][0]) + vRowOff * 4;
        const uint32_t vBaseL = vBaseH + 16 * 68 * 4;

        // ---- MMA1: D[16 n-steps][4] ----
        float D[16][4];
#pragma unroll
        for (int ns = 0; ns < 16; ns++) {
            uint32_t b0, b1, b2, b3;
            ldsm4(b0, b1, b2, b3, kBase + (uint32_t)ns * 640);   // 8 rows * 80B
            float d0 = 0.f, d1 = 0.f, d2 = 0.f, d3 = 0.f;
            mma_bf16(d0, d1, d2, d3, a_q[0], a_q[1], a_q[2], a_q[3], b0, b1);
            mma_bf16(d0, d1, d2, d3, a_q[4], a_q[5], a_q[6], a_q[7], b2, b3);
            D[ns][0] = d0; D[ns][1] = d1; D[ns][2] = d2; D[ns][3] = d3;
        }

        // ---- relu + fp16 pack + MMA2 (2-term) ----
#pragma unroll
        for (int kb = 0; kb < 8; kb++) {
            float c0 = fmaxf(D[2 * kb][0], 0.f), c1 = fmaxf(D[2 * kb][1], 0.f);
            float c2 = fmaxf(D[2 * kb][2], 0.f), c3 = fmaxf(D[2 * kb][3], 0.f);
            float e0 = fmaxf(D[2 * kb + 1][0], 0.f), e1 = fmaxf(D[2 * kb + 1][1], 0.f);
            float e2 = fmaxf(D[2 * kb + 1][2], 0.f), e3 = fmaxf(D[2 * kb + 1][3], 0.f);

            uint32_t sh0 = packh(c0, c1), sh1 = packh(c2, c3);
            uint32_t sh2 = packh(e0, e1), sh3 = packh(e2, e3);

            uint32_t vh0, vh1, wh0, wh1, vl0, vl1, wl0, wl1;
            ldsm4(vh0, vh1, wh0, wh1, vBaseH + (uint32_t)kb * 32);
            ldsm4(vl0, vl1, wl0, wl1, vBaseL + (uint32_t)kb * 32);

            mma_f16(O0, sh0, sh1, sh2, sh3, vh0, vh1);
            mma_f16(O0, sh0, sh1, sh2, sh3, vl0, vl1);
            mma_f16(O1, sh0, sh1, sh2, sh3, wh0, wh1);
            mma_f16(O1, sh0, sh1, sh2, sh3, wl0, wl1);
        }
        __syncthreads();
    }

    // ---- epilogue ----
    {
        float* po = g_part + (size_t)my * (N_TOK * NF);
        const int r0 = rq;
        const int f0 = l4 * 2;
        po[(size_t)r0 * NF + f0]           = O0[0];
        po[(size_t)r0 * NF + f0 + 1]       = O0[1];
        po[(size_t)(r0 + 8) * NF + f0]     = O0[2];
        po[(size_t)(r0 + 8) * NF + f0 + 1] = O0[3];
        if (l4 == 0) {
            po[(size_t)r0 * NF + 8]       = O1[0];
            po[(size_t)r0 * NF + 9]       = O1[1];
            po[(size_t)(r0 + 8) * NF + 8] = O1[2];
            po[(size_t)(r0 + 8) * NF + 9] = O1[3];
        }
    }
}

// ---------------- Kernel 3: deterministic reduce + output permute ----------------
__global__ __launch_bounds__(256) void reduce_kernel(float* __restrict__ out)
{
    const int idx = blockIdx.x * blockDim.x + threadIdx.x;   // < 81920
    const int hw  = idx & 1023;
    const int f   = (idx >> 10) % NF;
    const int t   = idx / (NF * 1024);
    const int n   = t * 1024 + hw;
    float s = 0.f;
#pragma unroll
    for (int c = 0; c < M_SPLIT; c++)
        s += g_part[(size_t)c * (N_TOK * NF) + n * NF + f];
    out[idx] = s;
}

extern "C" void kernel_launch(void* const* d_in, const int* in_sizes, int n_in,
                              void* d_out, int out_size)
{
    const float* in1 = (const float*)d_in[0];
    const float* in2 = (const float*)d_in[1];
    const float* w1  = (const float*)d_in[2];
    const float* b1  = (const float*)d_in[3];
    const float* w2  = (const float*)d_in[4];
    const float* b2  = (const float*)d_in[5];
    const float* w3  = (const float*)d_in[6];
    const float* b3  = (const float*)d_in[7];

    dim3 pgrid(N_TOK / 64, 3);
    proj_kernel<<<pgrid, 256>>>(in1, in2, w1, b1, w2, b2, w3, b3);

    dim3 agrid(N_TOK / 128, M_SPLIT);
    attn_kernel<<<agrid, 256>>>();

    reduce_kernel<<<(N_TOK * NF) / 256, 256>>>((float*)d_out);
}